// round 7
// baseline (speedup 1.0000x reference)
#include <cuda_runtime.h>

// SmartDerivatives R7: R6 row-parallel consumer + cp.async-staged left.
// R6 was capped at 3.9TB/s by L1tex replays of stride-24B LDG.64 (6 lines
// per request). Here left is streamed into shared via coalesced cp.async
// in 5 double-buffered "bands"; each band = mirrored row-pairs
// (rows 10c..10c+9  and  98-10c..89-10c) = exactly TWO contiguous desc
// ranges (<=1000 descs, 24KB). Warp w owns pair (10c+w, 98-(10c+w)):
// balanced, rows never cross bands. Consumer reads shared (stride-6-word
// float2 LDS: conflict-free per 16-lane phase); j-side bins unchanged.

constexpr int NA    = 100;
constexpr int D     = 4950;
constexpr int E     = D * 6;
constexpr int S3    = NA * 3;          // 300
constexpr int WARPS = 10;
constexpr int T     = WARPS * 32;      // 320
constexpr int BANDS = 5;
constexpr int BANDF = 6000;            // max floats per band (1000 descs)

// rowbase(r) = r*(199-r)/2
__host__ __device__ constexpr int rowbase(int r) { return r * (199 - r) / 2; }

// Band tables (descs): front rows [10c,10c+10), back rows [89-10c,99-10c)
// (band 4 back = rows [50,59)).
__device__ __constant__ int FS[BANDS] = {0, 945, 1790, 2535, 3180};
__device__ __constant__ int FL[BANDS] = {945, 845, 745, 645, 545};
__device__ __constant__ int BS[BANDS] = {4895, 4740, 4485, 4130, 3725};
__device__ __constant__ int BL[BANDS] = {55, 155, 255, 355, 405};

__device__ __forceinline__ unsigned smaddr(const void* p) {
    return (unsigned)__cvta_generic_to_shared(p);
}
__device__ __forceinline__ void cp8(unsigned d, const void* s) {
    asm volatile("cp.async.ca.shared.global [%0], [%1], 8;" :: "r"(d), "l"(s));
}

// stage one band: two contiguous float2 ranges -> shared buffer
__device__ __forceinline__ void stage_band(float* buf, const float* lb,
                                           int c, int t) {
    const float2* __restrict__ g = reinterpret_cast<const float2*>(lb);
    float2* b2 = reinterpret_cast<float2*>(buf);
    const int nf = FL[c] * 3, nb = BL[c] * 3;     // float2 counts
    const int fs = FS[c] * 3, bs = BS[c] * 3;
    for (int i = t; i < nf; i += T) cp8(smaddr(b2 + i), g + fs + i);
    for (int i = t; i < nb; i += T) cp8(smaddr(b2 + nf + i), g + bs + i);
}

// consume one triu row from shared
__device__ __forceinline__ void process_row(
    int i, int lane,
    const float* __restrict__ lrow,   // shared, 6 floats per desc
    const float* __restrict__ xb,     // global x row
    float* __restrict__ ca, float* __restrict__ rowout)
{
    const int base = rowbase(i);
    const int len  = NA - 1 - i;

    float r0 = 0.f, r1 = 0.f, r2 = 0.f;

    #pragma unroll 2
    for (int m = lane; m < len; m += 32) {
        const float2* lp = reinterpret_cast<const float2*>(lrow + 6 * m);
        const float2 l01 = lp[0];
        const float2 l23 = lp[1];
        const float2 l45 = lp[2];
        const float  xv  = __ldg(xb + base + m);

        r0 = fmaf(l01.x, xv, r0);
        r1 = fmaf(l01.y, xv, r1);
        r2 = fmaf(l23.x, xv, r2);

        float* cj = ca + (i + 1 + m) * 3;        // j unique per lane
        cj[0] += l23.y * xv;
        cj[1] += l45.x * xv;
        cj[2] += l45.y * xv;
    }

    #pragma unroll
    for (int off = 16; off; off >>= 1) {
        r0 += __shfl_down_sync(0xffffffffu, r0, off);
        r1 += __shfl_down_sync(0xffffffffu, r1, off);
        r2 += __shfl_down_sync(0xffffffffu, r2, off);
    }
    if (lane == 0) {
        rowout[i * 3 + 0] = r0;
        rowout[i * 3 + 1] = r1;
        rowout[i * 3 + 2] = r2;
    }
}

__global__ void __launch_bounds__(T)
smart_derivatives_kernel(const float* __restrict__ x,
                         const float* __restrict__ left,
                         float* __restrict__ out) {
    extern __shared__ __align__(16) float ls[];   // [2][BANDF] = 48 KB
    __shared__ float colacc[WARPS][S3];           // 12 KB
    __shared__ float rowout[S3];                  // 1.2 KB

    const int b    = blockIdx.x;
    const int t    = threadIdx.x;
    const int w    = t >> 5;
    const int lane = t & 31;

    for (int i = t; i < WARPS * S3; i += T) (&colacc[0][0])[i] = 0.0f;
    if (t < S3) rowout[t] = 0.0f;

    const float* __restrict__ lb = left + (size_t)b * E;
    const float* __restrict__ xb = x + (size_t)b * D;
    float* __restrict__ ca = colacc[w];

    // prologue: band 0
    stage_band(ls, lb, 0, t);
    asm volatile("cp.async.commit_group;");

    #pragma unroll
    for (int c = 0; c < BANDS; ++c) {
        if (c + 1 < BANDS) {
            stage_band(ls + ((c + 1) & 1) * BANDF, lb, c + 1, t);
            asm volatile("cp.async.commit_group;");
            asm volatile("cp.async.wait_group 1;");
        } else {
            asm volatile("cp.async.wait_group 0;");
        }
        __syncthreads();

        const float* buf = ls + (c & 1) * BANDF;
        const int u = 10 * c + w;                 // pair-unit of this warp

        // front row u: buffer offset (rowbase(u) - FS[c]) * 6
        process_row(u, lane, buf + (rowbase(u) - FS[c]) * 6, xb, ca, rowout);

        // back row 98-u (absent only for u == 49)
        if (u < 49) {
            const int rb = 98 - u;
            const float* brow = buf + (FL[c] + (rowbase(rb) - BS[c])) * 6;
            process_row(rb, lane, brow, xb, ca, rowout);
        }
        __syncthreads();   // buf[c&1] is overwritten at iter c+1's issue
    }

    if (t < S3) {
        float s = rowout[t];
        #pragma unroll
        for (int ww = 0; ww < WARPS; ++ww) s += colacc[ww][t];
        out[(size_t)b * S3 + t] = s * s;
    }
}

extern "C" void kernel_launch(void* const* d_in, const int* in_sizes, int n_in,
                              void* d_out, int out_size) {
    const float* x    = (const float*)d_in[0];   // [BATCH, D] fp32
    const float* left = (const float*)d_in[1];   // [BATCH*E] fp32
    (void)in_sizes; (void)n_in; (void)out_size;

    const int dyn_smem = 2 * BANDF * (int)sizeof(float);   // 48 KB
    cudaFuncSetAttribute(smart_derivatives_kernel,
                         cudaFuncAttributeMaxDynamicSharedMemorySize, dyn_smem);

    float* out = (float*)d_out;                  // [BATCH, 300] fp32
    smart_derivatives_kernel<<<1024, T, dyn_smem>>>(x, left, out);
}

// round 8
// speedup vs baseline: 1.1488x; 1.1488x over previous
#include <cuda_runtime.h>

// SmartDerivatives R8: R6's direct-LDG row-parallel consumer, restructured for
// wave occupancy + conflict-free bins.
//  - 128-thread CTAs: 1024 frames all resident in ONE wave (7 CTAs/SM).
//  - colacc stored SoA [warp][dim][atom] -> j-side RMW lane stride = 4B,
//    bank-conflict-free (R6's AoS stride-12B was 3-way conflicted).
//  - Mirrored row pairs (base+w, base+7-w) per 8-row band: balanced warps.
// Each desc (i,j) read ONCE: slots 0..2 -> atom i (regs + shfl reduce),
// slots 3..5 -> atom j (warp-private bins). No atomics, no staging.

constexpr int NA    = 100;
constexpr int D     = 4950;
constexpr int E     = D * 6;
constexpr int S3    = NA * 3;        // 300
constexpr int WARPS = 4;
constexpr int T     = WARPS * 32;    // 128
constexpr int AP    = 128;           // padded atoms per bin plane

__device__ __forceinline__ void process_row(
    int i, int lane,
    const float* __restrict__ lb, const float* __restrict__ xb,
    float* __restrict__ c0, float* __restrict__ c1, float* __restrict__ c2,
    float* __restrict__ rowout)
{
    const int base = (i * (2 * NA - i - 1)) >> 1;   // row start desc
    const int len  = NA - 1 - i;

    float r0 = 0.f, r1 = 0.f, r2 = 0.f;

    #pragma unroll 2
    for (int m = lane; m < len; m += 32) {
        const int desc = base + m;
        const float2* lp = reinterpret_cast<const float2*>(lb + desc * 6);
        const float2 l01 = __ldg(lp);
        const float2 l23 = __ldg(lp + 1);
        const float2 l45 = __ldg(lp + 2);
        const float  xv  = __ldg(xb + desc);

        // atom-i side (slots 0..2): register accumulate
        r0 = fmaf(l01.x, xv, r0);
        r1 = fmaf(l01.y, xv, r1);
        r2 = fmaf(l23.x, xv, r2);

        // atom-j side (slots 3..5): j unique per lane, stride-1 banks
        const int j = i + 1 + m;
        c0[j] += l23.y * xv;
        c1[j] += l45.x * xv;
        c2[j] += l45.y * xv;
    }

    #pragma unroll
    for (int off = 16; off; off >>= 1) {
        r0 += __shfl_down_sync(0xffffffffu, r0, off);
        r1 += __shfl_down_sync(0xffffffffu, r1, off);
        r2 += __shfl_down_sync(0xffffffffu, r2, off);
    }
    if (lane == 0) {
        rowout[i * 3 + 0] = r0;
        rowout[i * 3 + 1] = r1;
        rowout[i * 3 + 2] = r2;
    }
}

__global__ void __launch_bounds__(T)
smart_derivatives_kernel(const float* __restrict__ x,
                         const float* __restrict__ left,
                         float* __restrict__ out) {
    __shared__ float colacc[WARPS][3][AP];   // 6 KB, SoA, conflict-free RMW
    __shared__ float rowout[S3];             // 1.2 KB

    const int b    = blockIdx.x;
    const int t    = threadIdx.x;
    const int w    = t >> 5;
    const int lane = t & 31;

    for (int i = t; i < WARPS * 3 * AP; i += T) (&colacc[0][0][0])[i] = 0.0f;
    for (int i = t; i < S3; i += T) rowout[i] = 0.0f;
    __syncthreads();

    const float* __restrict__ lb = left + (size_t)b * E;
    const float* __restrict__ xb = x + (size_t)b * D;
    float* __restrict__ c0 = colacc[w][0];
    float* __restrict__ c1 = colacc[w][1];
    float* __restrict__ c2 = colacc[w][2];

    // Mirrored pairs per 8-row band: rows (base+w) and (base+7-w);
    // pair lengths sum to a band constant -> balanced warps.
    for (int base = 0; base < NA - 1; base += 2 * WARPS) {
        const int i1 = base + w;
        const int i2 = base + (2 * WARPS - 1) - w;
        if (i1 < NA - 1) process_row(i1, lane, lb, xb, c0, c1, c2, rowout);
        if (i2 < NA - 1) process_row(i2, lane, lb, xb, c0, c1, c2, rowout);
    }
    __syncthreads();

    // combine: out(a,d) = (rowout + sum_w colacc[w][d][a])^2
    for (int idx = t; idx < S3; idx += T) {
        const int a = idx / 3;
        const int d = idx - 3 * a;
        float s = rowout[idx];
        #pragma unroll
        for (int ww = 0; ww < WARPS; ++ww) s += colacc[ww][d][a];
        out[(size_t)b * S3 + idx] = s * s;
    }
}

extern "C" void kernel_launch(void* const* d_in, const int* in_sizes, int n_in,
                              void* d_out, int out_size) {
    const float* x    = (const float*)d_in[0];   // [BATCH, D] fp32
    const float* left = (const float*)d_in[1];   // [BATCH*E] fp32
    (void)in_sizes; (void)n_in; (void)out_size;

    float* out = (float*)d_out;                  // [BATCH, 300] fp32
    smart_derivatives_kernel<<<1024, T>>>(x, left, out);
}